// round 7
// baseline (speedup 1.0000x reference)
#include <cuda_runtime.h>
#include <math.h>
#include <stdint.h>

// Problem constants
#define Bb 8
#define Ss 512
#define Ll 512
#define Ee 768
#define Hh 12
#define HDd 64

#define NELE (Bb * Ss * Ee)                       // 3145728
#define NSC  ((size_t)Bb * Hh * Ss * Ll)          // 25165824

typedef unsigned short u16;

// ---------------------------------------------------------------------------
// Scratch (device globals — no allocation allowed)
// ---------------------------------------------------------------------------
__device__ float g_kx [NELE];
__device__ float g_tmp[NELE];
__device__ float g_Y  [NELE];
__device__ float g_Z  [NELE];
__device__ float g_sc [NSC];

__device__ u16 g_Xh[NELE],   g_Xl[NELE];
__device__ u16 g_ench[NELE], g_encl[NELE];
__device__ u16 g_kxh[NELE],  g_kxl[NELE];
__device__ u16 g_qxh[NELE],  g_qxl[NELE];
__device__ u16 g_kxTh[NELE], g_kxTl[NELE];       // [(b*H+h)*64+d][l]
__device__ u16 g_atth[NELE], g_attl[NELE];
__device__ u16 g_hidh[NELE], g_hidl[NELE];
__device__ u16 g_Yh[NELE],   g_Yl[NELE];
__device__ u16 g_Zh[NELE],   g_Zl[NELE];
__device__ u16 g_sch[NSC],   g_scl[NSC];
__device__ u16 g_wp0h[Ee*Ee], g_wp0l[Ee*Ee];
__device__ u16 g_wp1h[Ee*Ee], g_wp1l[Ee*Ee];
__device__ u16 g_wp2h[Ee*Ee], g_wp2l[Ee*Ee];
__device__ u16 g_wp3h[Ee*Ee], g_wp3l[Ee*Ee];
__device__ u16 g_pT1h[Ee*Ee], g_pT1l[Ee*Ee];
__device__ u16 g_pT2h[Ee*Ee], g_pT2l[Ee*Ee];
__device__ u16 g_fT1h[Ee*Ee], g_fT1l[Ee*Ee];
__device__ u16 g_fT2h[Ee*Ee], g_fT2l[Ee*Ee];

// ---------------------------------------------------------------------------
// fp32 <-> bf16 hi/lo split helpers
// ---------------------------------------------------------------------------
__device__ __forceinline__ u16 f2bf(float f) {
    unsigned u = __float_as_uint(f);
    u += 0x7FFFu + ((u >> 16) & 1u);
    return (u16)(u >> 16);
}
__device__ __forceinline__ float bf2f(u16 h) {
    return __uint_as_float(((unsigned)h) << 16);
}
__device__ __forceinline__ void split1(float x, u16 &h, u16 &l) {
    h = f2bf(x);
    l = f2bf(x - bf2f(h));
}
__device__ __forceinline__ void split2(float x, float y, unsigned &hi, unsigned &lo) {
    u16 hx, lx, hy, ly;
    split1(x, hx, lx); split1(y, hy, ly);
    hi = (unsigned)hx | ((unsigned)hy << 16);
    lo = (unsigned)lx | ((unsigned)ly << 16);
}

__device__ __forceinline__ void mma16816(float* c, const unsigned* a, unsigned b0, unsigned b1) {
    asm volatile(
        "mma.sync.aligned.m16n8k16.row.col.f32.bf16.bf16.f32 "
        "{%0,%1,%2,%3}, {%4,%5,%6,%7}, {%8,%9}, {%0,%1,%2,%3};\n"
        : "+f"(c[0]), "+f"(c[1]), "+f"(c[2]), "+f"(c[3])
        : "r"(a[0]), "r"(a[1]), "r"(a[2]), "r"(a[3]), "r"(b0), "r"(b1));
}

__device__ __forceinline__ void ldsm4(unsigned &r0, unsigned &r1, unsigned &r2, unsigned &r3,
                                      uint32_t a) {
    asm volatile("ldmatrix.sync.aligned.m8n8.x4.shared.b16 {%0,%1,%2,%3}, [%4];"
                 : "=r"(r0), "=r"(r1), "=r"(r2), "=r"(r3) : "r"(a));
}

__device__ __forceinline__ uint32_t s2u32(const void* p) {
    uint32_t a;
    asm("{ .reg .u64 t; cvta.to.shared.u64 t, %1; cvt.u32.u64 %0, t; }" : "=r"(a) : "l"(p));
    return a;
}

// ---------------------------------------------------------------------------
// Prep kernels
// ---------------------------------------------------------------------------
__global__ void pack_w_split(const float* __restrict__ w,
                             u16* __restrict__ oh, u16* __restrict__ ol) {
    int idx = blockIdx.x * blockDim.x + threadIdx.x;
    if (idx >= Ee * Ee) return;
    int n = idx / Ee, e = idx % Ee;
    int h = n / HDd, d = n % HDd;
    split1(w[((size_t)h * Ee + e) * HDd + d], oh[idx], ol[idx]);
}

__global__ void split_kernel(const float* __restrict__ in,
                             u16* __restrict__ oh, u16* __restrict__ ol, int n4) {
    int i = blockIdx.x * blockDim.x + threadIdx.x;
    if (i >= n4) return;
    float4 v = ((const float4*)in)[i];
    unsigned h0, l0, h1, l1;
    split2(v.x, v.y, h0, l0);
    split2(v.z, v.w, h1, l1);
    ((uint2*)oh)[i] = make_uint2(h0, h1);
    ((uint2*)ol)[i] = make_uint2(l0, l1);
}

__global__ void transpose768_split(const float* __restrict__ in,
                                   u16* __restrict__ oh, u16* __restrict__ ol) {
    __shared__ float t[32][33];
    int x0 = blockIdx.x * 32, y0 = blockIdx.y * 32;
    int tx = threadIdx.x, ty = threadIdx.y;
#pragma unroll
    for (int i = 0; i < 32; i += 8)
        t[ty + i][tx] = in[(size_t)(y0 + ty + i) * Ee + x0 + tx];
    __syncthreads();
#pragma unroll
    for (int i = 0; i < 32; i += 8) {
        size_t o = (size_t)(x0 + ty + i) * Ee + y0 + tx;
        split1(t[tx][ty + i], oh[o], ol[o]);
    }
}

__global__ void transpose_kx_split(const float* __restrict__ kx,
                                   u16* __restrict__ oh, u16* __restrict__ ol) {
    __shared__ float t[32][33];
    int bh = blockIdx.z;
    int b = bh / Hh, h = bh % Hh;
    int l0 = blockIdx.x * 32, d0 = blockIdx.y * 32;
    int tx = threadIdx.x, ty = threadIdx.y;
#pragma unroll
    for (int i = 0; i < 32; i += 8)
        t[ty + i][tx] = kx[(size_t)(b * Ss + l0 + ty + i) * Ee + h * HDd + d0 + tx];
    __syncthreads();
#pragma unroll
    for (int i = 0; i < 32; i += 8) {
        size_t o = ((size_t)bh * HDd + d0 + ty + i) * Ss + l0 + tx;
        split1(t[tx][ty + i], oh[o], ol[o]);
    }
}

// ---------------------------------------------------------------------------
// Pre-split bf16x3 NT GEMM: mma.sync + ldmatrix.x4 + 4-stage cp.async.
//   C = act(alpha * A@B^T (+bias))
// A hi/lo [m][k] (lda), B hi/lo [n][k] (ldb); fp32 Cf and/or hi/lo out.
// Requires M%128==0, N%BN==0, K%32==0, 16B-aligned rows.
// Stage layout (shorts): [A_hi | A_lo | B_hi | B_lo], rows padded to 40.
// ---------------------------------------------------------------------------
template <int BN>
__global__ __launch_bounds__(256) void gemm_pre(
    const u16* __restrict__ Ah, const u16* __restrict__ Al, int lda,
    const u16* __restrict__ Bh, const u16* __restrict__ Bl, int ldb,
    float* __restrict__ Cf, u16* __restrict__ Chi, u16* __restrict__ Clo,
    int ldc, int K, float alpha, const float* __restrict__ bias, int act,
    int divz, long sA1, long sA2, long sB1, long sB2, long sC1, long sC2)
{
    constexpr int BM = 128, BK = 32, BKp = 40;
    constexpr int ASZ = BM * BKp, BSZ = BN * BKp;       // shorts per array
    constexpr int STG = 2 * (ASZ + BSZ);                // shorts per stage
    constexpr int WN = 32, WM = (BN == 128) ? 64 : 32;
    constexpr int MF = WM / 16, NF = WN / 8;
    extern __shared__ __align__(16) u16 smx[];

    const int z = blockIdx.z, z1 = z / divz, z2 = z % divz;
    const long aoff = z1 * sA1 + z2 * sA2;
    const long boff = z1 * sB1 + z2 * sB2;
    const long coff = z1 * sC1 + z2 * sC2;
    Ah += aoff; Al += aoff; Bh += boff; Bl += boff;

    const int tid = threadIdx.x, w = tid >> 5, lane = tid & 31;
    const int g = lane >> 2, tig = lane & 3;
    const int bm0 = blockIdx.y * BM, bn0 = blockIdx.x * BN;
    const int wm0 = (w / (BN / WN)) * WM;
    const int wn0 = (w % (BN / WN)) * WN;

    const uint32_t smem0 = s2u32(smx);
    // ldmatrix lane-address offsets (bytes), reproducing the scalar frag map:
    //  A x4 groups: [m0:8,kLo],[m8:16,kLo],[m0:8,kHi],[m8:16,kHi]
    //  B x4 groups: [nf,kLo],[nf,kHi],[nf+1,kLo],[nf+1,kHi]
    const int r8 = lane & 7, grp = lane >> 3;
    const uint32_t offA = (uint32_t)(((r8 + (grp & 1) * 8) * BKp + (grp >> 1) * 8) * 2);
    const uint32_t offB = (uint32_t)(((r8 + (lane >> 4) * 8) * BKp + ((grp & 1)) * 8) * 2);

    float cacc[MF][NF][4];
#pragma unroll
    for (int mf = 0; mf < MF; mf++)
#pragma unroll
        for (int nf = 0; nf < NF; nf++)
#pragma unroll
            for (int i = 0; i < 4; i++) cacc[mf][nf][i] = 0.0f;

    auto load_stage = [&](int s, int k0) {
        u16* base = smx + s * STG;
#pragma unroll
        for (int arr = 0; arr < 2; arr++) {
            u16* d0 = base + arr * ASZ;
            const u16* src = arr ? Al : Ah;
            for (int c = tid; c < BM * 4; c += 256) {
                int r = c >> 2, ch = c & 3;
                uint32_t da = (uint32_t)__cvta_generic_to_shared(d0 + r * BKp + ch * 8);
                const void* sa = src + (size_t)(bm0 + r) * lda + k0 + ch * 8;
                asm volatile("cp.async.cg.shared.global [%0], [%1], 16;\n" :: "r"(da), "l"(sa));
            }
        }
#pragma unroll
        for (int arr = 0; arr < 2; arr++) {
            u16* d0 = base + 2 * ASZ + arr * BSZ;
            const u16* src = arr ? Bl : Bh;
            for (int c = tid; c < BN * 4; c += 256) {
                int r = c >> 2, ch = c & 3;
                uint32_t da = (uint32_t)__cvta_generic_to_shared(d0 + r * BKp + ch * 8);
                const void* sa = src + (size_t)(bn0 + r) * ldb + k0 + ch * 8;
                asm volatile("cp.async.cg.shared.global [%0], [%1], 16;\n" :: "r"(da), "l"(sa));
            }
        }
        asm volatile("cp.async.commit_group;\n");
    };

    const int T = K / BK;
    for (int s = 0; s < 3 && s < T; s++) load_stage(s, s * BK);

    for (int t = 0; t < T; t++) {
        if (t < T - 2)       asm volatile("cp.async.wait_group 2;\n" ::: "memory");
        else if (t == T - 2) asm volatile("cp.async.wait_group 1;\n" ::: "memory");
        else                 asm volatile("cp.async.wait_group 0;\n" ::: "memory");
        __syncthreads();
        if (t + 3 < T) load_stage((t + 3) & 3, (t + 3) * BK);

        const uint32_t sb    = smem0 + (uint32_t)((t & 3) * STG * 2);
        const uint32_t aBase = sb + (uint32_t)(wm0 * BKp * 2) + offA;
        const uint32_t bBase = sb + (uint32_t)(2 * ASZ * 2 + wn0 * BKp * 2) + offB;

#pragma unroll
        for (int ks = 0; ks < 2; ks++) {
            unsigned bh[NF][2], bl[NF][2];
#pragma unroll
            for (int p = 0; p < NF / 2; p++) {
                uint32_t ad = bBase + (uint32_t)((p * 16 * BKp + ks * 16) * 2);
                ldsm4(bh[2*p][0], bh[2*p][1], bh[2*p+1][0], bh[2*p+1][1], ad);
                ldsm4(bl[2*p][0], bl[2*p][1], bl[2*p+1][0], bl[2*p+1][1], ad + BSZ * 2);
            }
#pragma unroll
            for (int mf = 0; mf < MF; mf++) {
                uint32_t ad = aBase + (uint32_t)((mf * 16 * BKp + ks * 16) * 2);
                unsigned ah[4], al[4];
                ldsm4(ah[0], ah[1], ah[2], ah[3], ad);
                ldsm4(al[0], al[1], al[2], al[3], ad + ASZ * 2);
#pragma unroll
                for (int nf = 0; nf < NF; nf++) {
                    mma16816(cacc[mf][nf], ah, bh[nf][0], bh[nf][1]);   // hi*hi
                    mma16816(cacc[mf][nf], al, bh[nf][0], bh[nf][1]);   // lo*hi
                    mma16816(cacc[mf][nf], ah, bl[nf][0], bl[nf][1]);   // hi*lo
                }
            }
        }
        // no trailing sync: next iteration's post-wait __syncthreads orders
        // this stage's readers before it is overwritten 3 iterations later.
    }

    // Epilogue
#pragma unroll
    for (int mf = 0; mf < MF; mf++) {
#pragma unroll
        for (int nf = 0; nf < NF; nf++) {
            int row = bm0 + wm0 + mf * 16 + g;
            int col = bn0 + wn0 + nf * 8 + tig * 2;
            float b0 = 0.f, b1 = 0.f;
            if (bias) { b0 = bias[col]; b1 = bias[col + 1]; }
            float v0 = cacc[mf][nf][0] * alpha + b0;
            float v1 = cacc[mf][nf][1] * alpha + b1;
            float v2 = cacc[mf][nf][2] * alpha + b0;
            float v3 = cacc[mf][nf][3] * alpha + b1;
            if (act) {
                v0 = 0.5f * v0 * (1.0f + erff(v0 * 0.70710678118654752f));
                v1 = 0.5f * v1 * (1.0f + erff(v1 * 0.70710678118654752f));
                v2 = 0.5f * v2 * (1.0f + erff(v2 * 0.70710678118654752f));
                v3 = 0.5f * v3 * (1.0f + erff(v3 * 0.70710678118654752f));
            }
            size_t o0 = coff + (size_t)row * ldc + col;
            size_t o1 = coff + (size_t)(row + 8) * ldc + col;
            if (Cf) {
                *(float2*)&Cf[o0] = make_float2(v0, v1);
                *(float2*)&Cf[o1] = make_float2(v2, v3);
            }
            if (Chi) {
                unsigned h0, l0, h1, l1;
                split2(v0, v1, h0, l0);
                split2(v2, v3, h1, l1);
                *(unsigned*)&Chi[o0] = h0; *(unsigned*)&Clo[o0] = l0;
                *(unsigned*)&Chi[o1] = h1; *(unsigned*)&Clo[o1] = l1;
            }
        }
    }
}

// ---------------------------------------------------------------------------
// Masked softmax: fp32 scores in, hi/lo bf16 probs out.
// ---------------------------------------------------------------------------
__global__ __launch_bounds__(256) void softmax_split_kernel(
    const float* __restrict__ scores,
    u16* __restrict__ ph, u16* __restrict__ pl,
    int mode, const int* __restrict__ vlens)
{
    const int row = blockIdx.x;               // (b*H + h)*S + q
    const int q = row % Ss;
    const int b = row / (Hh * Ss);
    const int valid = (mode == 0) ? (q + 1) : vlens[b];

    const float* p = scores + (size_t)row * Ll;
    const int t = threadIdx.x;
    float x0 = p[t];
    float x1 = p[t + 256];

    __shared__ float red[256];
    float m = -1e30f;
    if (t < valid) m = x0;
    if (t + 256 < valid) m = fmaxf(m, x1);
    red[t] = m; __syncthreads();
#pragma unroll
    for (int s = 128; s > 0; s >>= 1) {
        if (t < s) red[t] = fmaxf(red[t], red[t + s]);
        __syncthreads();
    }
    float mx = red[0];
    __syncthreads();

    float e0 = (t < valid) ? expf(x0 - mx) : 0.0f;
    float e1 = (t + 256 < valid) ? expf(x1 - mx) : 0.0f;
    red[t] = e0 + e1; __syncthreads();
#pragma unroll
    for (int s = 128; s > 0; s >>= 1) {
        if (t < s) red[t] += red[t + s];
        __syncthreads();
    }
    float inv = 1.0f / red[0];
    size_t o = (size_t)row * Ll;
    split1(e0 * inv, ph[o + t], pl[o + t]);
    split1(e1 * inv, ph[o + t + 256], pl[o + t + 256]);
}

// ---------------------------------------------------------------------------
// out = LayerNorm(a + b); optional hi/lo bf16 copy of out.
// ---------------------------------------------------------------------------
__global__ __launch_bounds__(256) void add_ln_kernel(
    const float* __restrict__ a, const float* __restrict__ b,
    const float* __restrict__ w, const float* __restrict__ bs,
    float* __restrict__ out,
    u16* __restrict__ oh, u16* __restrict__ ol)
{
    const int row = blockIdx.x;
    const float* pa = a + (size_t)row * Ee;
    const float* pb = b + (size_t)row * Ee;
    const int t = threadIdx.x;

    float x[3];
    float s = 0.0f;
#pragma unroll
    for (int i = 0; i < 3; i++) {
        x[i] = pa[t + 256 * i] + pb[t + 256 * i];
        s += x[i];
    }
    __shared__ float red[256];
    red[t] = s; __syncthreads();
#pragma unroll
    for (int st = 128; st > 0; st >>= 1) {
        if (t < st) red[t] += red[t + st];
        __syncthreads();
    }
    float mean = red[0] * (1.0f / Ee);
    __syncthreads();

    float v = 0.0f;
#pragma unroll
    for (int i = 0; i < 3; i++) {
        float d = x[i] - mean;
        v += d * d;
    }
    red[t] = v; __syncthreads();
#pragma unroll
    for (int st = 128; st > 0; st >>= 1) {
        if (t < st) red[t] += red[t + st];
        __syncthreads();
    }
    float var = red[0] * (1.0f / Ee);
    float inv = rsqrtf(var + 1e-12f);

#pragma unroll
    for (int i = 0; i < 3; i++) {
        int c = t + 256 * i;
        float o = w[c] * (x[i] - mean) * inv + bs[c];
        size_t off = (size_t)row * Ee + c;
        out[off] = o;
        if (oh) split1(o, oh[off], ol[off]);
    }
}

// ---------------------------------------------------------------------------
// Orchestration
// ---------------------------------------------------------------------------
extern "C" void kernel_launch(void* const* d_in, const int* in_sizes, int n_in,
                              void* d_out, int out_size)
{
    const float* X       = (const float*)d_in[0];
    const float* enc     = (const float*)d_in[1];
    const int*   vlens   = (const int*)  d_in[2];
    const float* w_kx1   = (const float*)d_in[3];
    const float* w_qx1   = (const float*)d_in[4];
    const float* proj1_w = (const float*)d_in[5];
    const float* proj1_b = (const float*)d_in[6];
    const float* ln1_w   = (const float*)d_in[7];
    const float* ln1_b   = (const float*)d_in[8];
    const float* w_kx2   = (const float*)d_in[9];
    const float* w_qx2   = (const float*)d_in[10];
    const float* proj2_w = (const float*)d_in[11];
    const float* proj2_b = (const float*)d_in[12];
    const float* ln2_w   = (const float*)d_in[13];
    const float* ln2_b   = (const float*)d_in[14];
    const float* ffn_w1  = (const float*)d_in[15];
    const float* ffn_b1  = (const float*)d_in[16];
    const float* ffn_w2  = (const float*)d_in[17];
    const float* ffn_b2  = (const float*)d_in[18];
    const float* ln3_w   = (const float*)d_in[19];
    const float* ln3_b   = (const float*)d_in[20];

#define SYM(p, s) cudaGetSymbolAddress((void**)&p, s)
    float *kx, *tmp, *Y, *Z, *sc;
    u16 *Xh,*Xl,*ench,*encl,*kxh,*kxl,*qxh,*qxl,*kxTh,*kxTl;
    u16 *atth,*attl,*hidh,*hidl,*Yh,*Yl,*Zh,*Zl,*sch,*scl;
    u16 *wp0h,*wp0l,*wp1h,*wp1l,*wp2h,*wp2l,*wp3h,*wp3l;
    u16 *pT1h,*pT1l,*pT2h,*pT2l,*fT1h,*fT1l,*fT2h,*fT2l;
    SYM(kx, g_kx); SYM(tmp, g_tmp); SYM(Y, g_Y); SYM(Z, g_Z); SYM(sc, g_sc);
    SYM(Xh, g_Xh); SYM(Xl, g_Xl); SYM(ench, g_ench); SYM(encl, g_encl);
    SYM(kxh, g_kxh); SYM(kxl, g_kxl); SYM(qxh, g_qxh); SYM(qxl, g_qxl);
    SYM(kxTh, g_kxTh); SYM(kxTl, g_kxTl);
    SYM(atth, g_atth); SYM(attl, g_attl); SYM(hidh, g_hidh); SYM(hidl, g_hidl);
    SYM(Yh, g_Yh); SYM(Yl, g_Yl); SYM(Zh, g_Zh); SYM(Zl, g_Zl);
    SYM(sch, g_sch); SYM(scl, g_scl);
    SYM(wp0h, g_wp0h); SYM(wp0l, g_wp0l); SYM(wp1h, g_wp1h); SYM(wp1l, g_wp1l);
    SYM(wp2h, g_wp2h); SYM(wp2l, g_wp2l); SYM(wp3h, g_wp3h); SYM(wp3l, g_wp3l);
    SYM(pT1h, g_pT1h); SYM(pT1l, g_pT1l); SYM(pT2h, g_pT2h); SYM(pT2l, g_pT2l);
    SYM(fT1h, g_fT1h); SYM(fT1l, g_fT1l); SYM(fT2h, g_fT2h); SYM(fT2l, g_fT2l);
#undef SYM

    const int  M    = Bb * Ss;            // 4096
    const long SE   = (long)Ss * Ee;
    const long SL   = (long)Ss * Ll;
    const long HSL  = (long)Hh * SL;
    const long HDS  = (long)HDd * Ss;
    const long HHDS = (long)Hh * HDS;

    auto* G_BIG = gemm_pre<128>;
    auto* G_AV  = gemm_pre<64>;
    // 4 stages: stage shorts = 2*(128*40 + BN*40); bytes = *2
    const int SM_BIG = 4 * 2 * (128 * 40 + 128 * 40) * 2;   // 163840 B
    const int SM_AV  = 4 * 2 * (128 * 40 + 64 * 40) * 2;    // 122880 B
    cudaFuncSetAttribute(G_BIG, cudaFuncAttributeMaxDynamicSharedMemorySize, SM_BIG);
    cudaFuncSetAttribute(G_AV,  cudaFuncAttributeMaxDynamicSharedMemorySize, SM_AV);

    dim3 gridL(Ee / 128, M / 128, 1);
    dim3 gridS(Ll / 128, Ss / 128, Bb * Hh);
    dim3 gridAV(1, Ss / 128, Bb * Hh);
    dim3 tb(32, 8);
    dim3 gridT768(Ee / 32, Ee / 32, 1);
    dim3 gridTK(Ss / 32, HDd / 32, Bb * Hh);
    const int pblk = (Ee * Ee + 255) / 256;
    const int sblk = (NELE / 4 + 255) / 256;

    // --- prep ---------------------------------------------------------------
    pack_w_split<<<pblk, 256>>>(w_kx1, wp0h, wp0l);
    pack_w_split<<<pblk, 256>>>(w_qx1, wp1h, wp1l);
    split_kernel<<<sblk, 256>>>(X, Xh, Xl, NELE / 4);
    pack_w_split<<<pblk, 256>>>(w_kx2, wp2h, wp2l);
    pack_w_split<<<pblk, 256>>>(w_qx2, wp3h, wp3l);

    // ===================== Self-attention =====================
    G_BIG<<<gridL, 256, SM_BIG>>>(Xh, Xl, Ee, wp0h, wp0l, Ee,
                                  kx, kxh, kxl, Ee, Ee, 1.0f, nullptr, 0,
                                  1, 0, 0, 0, 0, 0, 0);
    G_BIG<<<gridL, 256, SM_BIG>>>(Xh, Xl, Ee, wp1h, wp1l, Ee,
                                  nullptr, qxh, qxl, Ee, Ee, 1.0f, nullptr, 0,
                                  1, 0, 0, 0, 0, 0, 0);
    transpose_kx_split<<<gridTK, tb>>>(kx, kxTh, kxTl);
    G_BIG<<<gridS, 256, SM_BIG>>>(qxh, qxl, Ee, kxh, kxl, Ee,
                                  sc, nullptr, nullptr, Ll, HDd, 0.125f, nullptr, 0,
                                  Hh, SE, HDd, SE, HDd, HSL, SL);
    softmax_split_kernel<<<Bb * Hh * Ss, 256>>>(sc, sch, scl, 0, nullptr);
    G_AV<<<gridAV, 256, SM_AV>>>(sch, scl, Ll, kxTh, kxTl, Ss,
                                 nullptr, atth, attl, Ee, Ll, 1.0f, nullptr, 0,
                                 Hh, HSL, SL, HHDS, HDS, SE, HDd);
    transpose768_split<<<gridT768, tb>>>(proj1_w, pT1h, pT1l);
    G_BIG<<<gridL, 256, SM_BIG>>>(atth, attl, Ee, pT1h, pT1l, Ee,
                                  tmp, nullptr, nullptr, Ee, Ee, 1.0f, proj1_b, 0,
                                  1, 0, 0, 0, 0, 0, 0);
    add_ln_kernel<<<M, 256>>>(tmp, X, ln1_w, ln1_b, Y, Yh, Yl);

    // ===================== Cross-attention =====================
    split_kernel<<<sblk, 256>>>(enc, ench, encl, NELE / 4);
    G_BIG<<<gridL, 256, SM_BIG>>>(ench, encl, Ee, wp2h, wp2l, Ee,
                                  kx, kxh, kxl, Ee, Ee, 1.0f, nullptr, 0,
                                  1, 0, 0, 0, 0, 0, 0);
    G_BIG<<<gridL, 256, SM_BIG>>>(Yh, Yl, Ee, wp3h, wp3l, Ee,
                                  nullptr, qxh, qxl, Ee, Ee, 1.0f, nullptr, 0,
                                  1, 0, 0, 0, 0, 0, 0);
    transpose_kx_split<<<gridTK, tb>>>(kx, kxTh, kxTl);
    G_BIG<<<gridS, 256, SM_BIG>>>(qxh, qxl, Ee, kxh, kxl, Ee,
                                  sc, nullptr, nullptr, Ll, HDd, 0.125f, nullptr, 0,
                                  Hh, SE, HDd, SE, HDd, HSL, SL);
    softmax_split_kernel<<<Bb * Hh * Ss, 256>>>(sc, sch, scl, 1, vlens);
    G_AV<<<gridAV, 256, SM_AV>>>(sch, scl, Ll, kxTh, kxTl, Ss,
                                 nullptr, atth, attl, Ee, Ll, 1.0f, nullptr, 0,
                                 Hh, HSL, SL, HHDS, HDS, SE, HDd);
    transpose768_split<<<gridT768, tb>>>(proj2_w, pT2h, pT2l);
    G_BIG<<<gridL, 256, SM_BIG>>>(atth, attl, Ee, pT2h, pT2l, Ee,
                                  tmp, nullptr, nullptr, Ee, Ee, 1.0f, proj2_b, 0,
                                  1, 0, 0, 0, 0, 0, 0);
    add_ln_kernel<<<M, 256>>>(tmp, Y, ln2_w, ln2_b, Z, Zh, Zl);

    // ===================== FFN =====================
    transpose768_split<<<gridT768, tb>>>(ffn_w1, fT1h, fT1l);
    transpose768_split<<<gridT768, tb>>>(ffn_w2, fT2h, fT2l);
    G_BIG<<<gridL, 256, SM_BIG>>>(Zh, Zl, Ee, fT1h, fT1l, Ee,
                                  nullptr, hidh, hidl, Ee, Ee, 1.0f, ffn_b1, 1,
                                  1, 0, 0, 0, 0, 0, 0);
    G_BIG<<<gridL, 256, SM_BIG>>>(hidh, hidl, Ee, fT2h, fT2l, Ee,
                                  tmp, nullptr, nullptr, Ee, Ee, 1.0f, ffn_b2, 0,
                                  1, 0, 0, 0, 0, 0, 0);
    add_ln_kernel<<<M, 256>>>(tmp, Z, ln3_w, ln3_b, (float*)d_out, nullptr, nullptr);
}

// round 10
// speedup vs baseline: 1.0591x; 1.0591x over previous
#include <cuda_runtime.h>
#include <math.h>
#include <stdint.h>

// Problem constants
#define Bb 8
#define Ss 512
#define Ll 512
#define Ee 768
#define Hh 12
#define HDd 64

#define NELE (Bb * Ss * Ee)                       // 3145728
#define NSC  ((size_t)Bb * Hh * Ss * Ll)          // 25165824

typedef unsigned short u16;

// ---------------------------------------------------------------------------
// Scratch (device globals — no allocation allowed)
// ---------------------------------------------------------------------------
__device__ float g_kx [NELE];
__device__ float g_tmp[NELE];
__device__ float g_Y  [NELE];
__device__ float g_Z  [NELE];
__device__ float g_sc [NSC];

__device__ u16 g_Xh[NELE],   g_Xl[NELE];
__device__ u16 g_ench[NELE], g_encl[NELE];
__device__ u16 g_kxh[NELE],  g_kxl[NELE];
__device__ u16 g_qxh[NELE],  g_qxl[NELE];
__device__ u16 g_kxTh[NELE], g_kxTl[NELE];       // [(b*H+h)*64+d][l]
__device__ u16 g_atth[NELE], g_attl[NELE];
__device__ u16 g_hidh[NELE], g_hidl[NELE];
__device__ u16 g_Yh[NELE],   g_Yl[NELE];
__device__ u16 g_Zh[NELE],   g_Zl[NELE];
__device__ u16 g_sch[NSC],   g_scl[NSC];
__device__ u16 g_wp0h[Ee*Ee], g_wp0l[Ee*Ee];
__device__ u16 g_wp1h[Ee*Ee], g_wp1l[Ee*Ee];
__device__ u16 g_wp2h[Ee*Ee], g_wp2l[Ee*Ee];
__device__ u16 g_wp3h[Ee*Ee], g_wp3l[Ee*Ee];
__device__ u16 g_pT1h[Ee*Ee], g_pT1l[Ee*Ee];
__device__ u16 g_pT2h[Ee*Ee], g_pT2l[Ee*Ee];
__device__ u16 g_fT1h[Ee*Ee], g_fT1l[Ee*Ee];
__device__ u16 g_fT2h[Ee*Ee], g_fT2l[Ee*Ee];

// ---------------------------------------------------------------------------
// fp32 <-> bf16 hi/lo split helpers
// ---------------------------------------------------------------------------
__device__ __forceinline__ u16 f2bf(float f) {
    unsigned u = __float_as_uint(f);
    u += 0x7FFFu + ((u >> 16) & 1u);
    return (u16)(u >> 16);
}
__device__ __forceinline__ float bf2f(u16 h) {
    return __uint_as_float(((unsigned)h) << 16);
}
__device__ __forceinline__ void split1(float x, u16 &h, u16 &l) {
    h = f2bf(x);
    l = f2bf(x - bf2f(h));
}
__device__ __forceinline__ void split2(float x, float y, unsigned &hi, unsigned &lo) {
    u16 hx, lx, hy, ly;
    split1(x, hx, lx); split1(y, hy, ly);
    hi = (unsigned)hx | ((unsigned)hy << 16);
    lo = (unsigned)lx | ((unsigned)ly << 16);
}

__device__ __forceinline__ void mma16816(float* c, const unsigned* a, unsigned b0, unsigned b1) {
    asm volatile(
        "mma.sync.aligned.m16n8k16.row.col.f32.bf16.bf16.f32 "
        "{%0,%1,%2,%3}, {%4,%5,%6,%7}, {%8,%9}, {%0,%1,%2,%3};\n"
        : "+f"(c[0]), "+f"(c[1]), "+f"(c[2]), "+f"(c[3])
        : "r"(a[0]), "r"(a[1]), "r"(a[2]), "r"(a[3]), "r"(b0), "r"(b1));
}

__device__ __forceinline__ void ldsm4(unsigned &r0, unsigned &r1, unsigned &r2, unsigned &r3,
                                      uint32_t a) {
    asm volatile("ldmatrix.sync.aligned.m8n8.x4.shared.b16 {%0,%1,%2,%3}, [%4];"
                 : "=r"(r0), "=r"(r1), "=r"(r2), "=r"(r3) : "r"(a));
}

__device__ __forceinline__ uint32_t s2u32(const void* p) {
    uint32_t a;
    asm("{ .reg .u64 t; cvta.to.shared.u64 t, %1; cvt.u32.u64 %0, t; }" : "=r"(a) : "l"(p));
    return a;
}

// ---------------------------------------------------------------------------
// Prep kernels
// ---------------------------------------------------------------------------
__global__ void pack_w_split(const float* __restrict__ w,
                             u16* __restrict__ oh, u16* __restrict__ ol) {
    int idx = blockIdx.x * blockDim.x + threadIdx.x;
    if (idx >= Ee * Ee) return;
    int n = idx / Ee, e = idx % Ee;
    int h = n / HDd, d = n % HDd;
    split1(w[((size_t)h * Ee + e) * HDd + d], oh[idx], ol[idx]);
}

__global__ void split_kernel(const float* __restrict__ in,
                             u16* __restrict__ oh, u16* __restrict__ ol, int n4) {
    int i = blockIdx.x * blockDim.x + threadIdx.x;
    if (i >= n4) return;
    float4 v = ((const float4*)in)[i];
    unsigned h0, l0, h1, l1;
    split2(v.x, v.y, h0, l0);
    split2(v.z, v.w, h1, l1);
    ((uint2*)oh)[i] = make_uint2(h0, h1);
    ((uint2*)ol)[i] = make_uint2(l0, l1);
}

__global__ void transpose768_split(const float* __restrict__ in,
                                   u16* __restrict__ oh, u16* __restrict__ ol) {
    __shared__ float t[32][33];
    int x0 = blockIdx.x * 32, y0 = blockIdx.y * 32;
    int tx = threadIdx.x, ty = threadIdx.y;
#pragma unroll
    for (int i = 0; i < 32; i += 8)
        t[ty + i][tx] = in[(size_t)(y0 + ty + i) * Ee + x0 + tx];
    __syncthreads();
#pragma unroll
    for (int i = 0; i < 32; i += 8) {
        size_t o = (size_t)(x0 + ty + i) * Ee + y0 + tx;
        split1(t[tx][ty + i], oh[o], ol[o]);
    }
}

__global__ void transpose_kx_split(const float* __restrict__ kx,
                                   u16* __restrict__ oh, u16* __restrict__ ol) {
    __shared__ float t[32][33];
    int bh = blockIdx.z;
    int b = bh / Hh, h = bh % Hh;
    int l0 = blockIdx.x * 32, d0 = blockIdx.y * 32;
    int tx = threadIdx.x, ty = threadIdx.y;
#pragma unroll
    for (int i = 0; i < 32; i += 8)
        t[ty + i][tx] = kx[(size_t)(b * Ss + l0 + ty + i) * Ee + h * HDd + d0 + tx];
    __syncthreads();
#pragma unroll
    for (int i = 0; i < 32; i += 8) {
        size_t o = ((size_t)bh * HDd + d0 + ty + i) * Ss + l0 + tx;
        split1(t[tx][ty + i], oh[o], ol[o]);
    }
}

// ---------------------------------------------------------------------------
// Pre-split bf16x3 NT GEMM: mma.sync + ldmatrix.x4 + 4-stage cp.async.
//   C = act(alpha * A@B^T (+bias))
// mmode: 0 none; 1 causal-scores (skip block if bn0>=bm0+BM);
//        2 causal-AV (clamp K to bm0+BM); 3 pad-scores (skip if vl[z1]<=bn0);
//        4 pad-AV (clamp K to ceil(vl[z1]/BK)*BK).
// All skipped contributions are exactly 0 -> results bitwise identical.
// ---------------------------------------------------------------------------
template <int BN>
__global__ __launch_bounds__(256) void gemm_pre(
    const u16* __restrict__ Ah, const u16* __restrict__ Al, int lda,
    const u16* __restrict__ Bh, const u16* __restrict__ Bl, int ldb,
    float* __restrict__ Cf, u16* __restrict__ Chi, u16* __restrict__ Clo,
    int ldc, int K, float alpha, const float* __restrict__ bias, int act,
    int mmode, const int* __restrict__ vl,
    int divz, long sA1, long sA2, long sB1, long sB2, long sC1, long sC2)
{
    constexpr int BM = 128, BK = 32, BKp = 40;
    constexpr int ASZ = BM * BKp, BSZ = BN * BKp;       // shorts per array
    constexpr int STG = 2 * (ASZ + BSZ);                // shorts per stage
    constexpr int WN = 32, WM = (BN == 128) ? 64 : 32;
    constexpr int MF = WM / 16, NF = WN / 8;
    extern __shared__ __align__(16) u16 smx[];

    const int z = blockIdx.z, z1 = z / divz, z2 = z % divz;
    const long aoff = z1 * sA1 + z2 * sA2;
    const long boff = z1 * sB1 + z2 * sB2;
    const long coff = z1 * sC1 + z2 * sC2;
    Ah += aoff; Al += aoff; Bh += boff; Bl += boff;

    const int tid = threadIdx.x, w = tid >> 5, lane = tid & 31;
    const int g = lane >> 2, tig = lane & 3;
    const int bm0 = blockIdx.y * BM, bn0 = blockIdx.x * BN;
    const int wm0 = (w / (BN / WN)) * WM;
    const int wn0 = (w % (BN / WN)) * WN;

    // --- masked-structure work elimination (exact zeros only) ---------------
    int kmax = K;
    if (mmode == 1) {
        if (bn0 >= bm0 + BM) return;                       // fully-masked block
    } else if (mmode == 2) {
        kmax = bm0 + BM; if (kmax > K) kmax = K;           // probs[q,l>q]==0
    } else if (mmode == 3) {
        if (vl[z1] <= bn0) return;                         // fully-masked block
    } else if (mmode == 4) {
        int v = vl[z1];
        kmax = ((v + BK - 1) / BK) * BK;                   // probs[q,l>=v]==0
        if (kmax > K) kmax = K;
    }

    const uint32_t smem0 = s2u32(smx);
    const int r8 = lane & 7, grp = lane >> 3;
    const uint32_t offA = (uint32_t)(((r8 + (grp & 1) * 8) * BKp + (grp >> 1) * 8) * 2);
    const uint32_t offB = (uint32_t)(((r8 + (lane >> 4) * 8) * BKp + ((grp & 1)) * 8) * 2);

    float cacc[MF][NF][4];
#pragma unroll
    for (int mf = 0; mf < MF; mf++)
#pragma unroll
        for (int nf = 0; nf < NF; nf++)
#pragma unroll
            for (int i = 0; i < 4; i++) cacc[mf][nf][i] = 0.0f;

    auto load_stage = [&](int s, int k0) {
        u16* base = smx + s * STG;
#pragma unroll
        for (int arr = 0; arr < 2; arr++) {
            u16* d0 = base + arr * ASZ;
            const u16* src = arr ? Al : Ah;
            for (int c = tid; c < BM * 4; c += 256) {
                int r = c >> 2, ch = c & 3;
                uint32_t da = (uint32_t)__cvta_generic_to_shared(d0 + r * BKp + ch * 8);
                const void* sa = src + (size_t)(bm0 + r) * lda + k0 + ch * 8;
                asm volatile("cp.async.cg.shared.global [%0], [%1], 16;\n" :: "r"(da), "l"(sa));
            }
        }
#pragma unroll
        for (int arr = 0; arr < 2; arr++) {
            u16* d0 = base + 2 * ASZ + arr * BSZ;
            const u16* src = arr ? Bl : Bh;
            for (int c = tid; c < BN * 4; c += 256) {
                int r = c >> 2, ch = c & 3;
                uint32_t da = (uint32_t)__cvta_generic_to_shared(d0 + r * BKp + ch * 8);
                const void* sa = src + (size_t)(bn0 + r) * ldb + k0 + ch * 8;
                asm volatile("cp.async.cg.shared.global [%0], [%1], 16;\n" :: "r"(da), "l"(sa));
            }
        }
        asm volatile("cp.async.commit_group;\n");
    };

    const int T = kmax / BK;
    for (int s = 0; s < 3 && s < T; s++) load_stage(s, s * BK);

    for (int t = 0; t < T; t++) {
        if (t < T - 2)       asm volatile("cp.async.wait_group 2;\n" ::: "memory");
        else if (t == T - 2) asm volatile("cp.async.wait_group 1;\n" ::: "memory");
        else                 asm volatile("cp.async.wait_group 0;\n" ::: "memory");
        __syncthreads();
        if (t + 3 < T) load_stage((t + 3) & 3, (t + 3) * BK);

        const uint32_t sb    = smem0 + (uint32_t)((t & 3) * STG * 2);
        const uint32_t aBase = sb + (uint32_t)(wm0 * BKp * 2) + offA;
        const uint32_t bBase = sb + (uint32_t)(2 * ASZ * 2 + wn0 * BKp * 2) + offB;

#pragma unroll
        for (int ks = 0; ks < 2; ks++) {
            unsigned bh[NF][2], bl[NF][2];
#pragma unroll
            for (int p = 0; p < NF / 2; p++) {
                uint32_t ad = bBase + (uint32_t)((p * 16 * BKp + ks * 16) * 2);
                ldsm4(bh[2*p][0], bh[2*p][1], bh[2*p+1][0], bh[2*p+1][1], ad);
                ldsm4(bl[2*p][0], bl[2*p][1], bl[2*p+1][0], bl[2*p+1][1], ad + BSZ * 2);
            }
#pragma unroll
            for (int mf = 0; mf < MF; mf++) {
                uint32_t ad = aBase + (uint32_t)((mf * 16 * BKp + ks * 16) * 2);
                unsigned ah[4], al[4];
                ldsm4(ah[0], ah[1], ah[2], ah[3], ad);
                ldsm4(al[0], al[1], al[2], al[3], ad + ASZ * 2);
#pragma unroll
                for (int nf = 0; nf < NF; nf++) {
                    mma16816(cacc[mf][nf], ah, bh[nf][0], bh[nf][1]);   // hi*hi
                    mma16816(cacc[mf][nf], al, bh[nf][0], bh[nf][1]);   // lo*hi
                    mma16816(cacc[mf][nf], ah, bl[nf][0], bl[nf][1]);   // hi*lo
                }
            }
        }
    }

    // Epilogue
#pragma unroll
    for (int mf = 0; mf < MF; mf++) {
#pragma unroll
        for (int nf = 0; nf < NF; nf++) {
            int row = bm0 + wm0 + mf * 16 + g;
            int col = bn0 + wn0 + nf * 8 + tig * 2;
            float b0 = 0.f, b1 = 0.f;
            if (bias) { b0 = bias[col]; b1 = bias[col + 1]; }
            float v0 = cacc[mf][nf][0] * alpha + b0;
            float v1 = cacc[mf][nf][1] * alpha + b1;
            float v2 = cacc[mf][nf][2] * alpha + b0;
            float v3 = cacc[mf][nf][3] * alpha + b1;
            if (act) {
                v0 = 0.5f * v0 * (1.0f + erff(v0 * 0.70710678118654752f));
                v1 = 0.5f * v1 * (1.0f + erff(v1 * 0.70710678118654752f));
                v2 = 0.5f * v2 * (1.0f + erff(v2 * 0.70710678118654752f));
                v3 = 0.5f * v3 * (1.0f + erff(v3 * 0.70710678118654752f));
            }
            size_t o0 = coff + (size_t)row * ldc + col;
            size_t o1 = coff + (size_t)(row + 8) * ldc + col;
            if (Cf) {
                *(float2*)&Cf[o0] = make_float2(v0, v1);
                *(float2*)&Cf[o1] = make_float2(v2, v3);
            }
            if (Chi) {
                unsigned h0, l0, h1, l1;
                split2(v0, v1, h0, l0);
                split2(v2, v3, h1, l1);
                *(unsigned*)&Chi[o0] = h0; *(unsigned*)&Clo[o0] = l0;
                *(unsigned*)&Chi[o1] = h1; *(unsigned*)&Clo[o1] = l1;
            }
        }
    }
}

// ---------------------------------------------------------------------------
// Masked softmax: fp32 scores in, hi/lo bf16 probs out.
// ---------------------------------------------------------------------------
__global__ __launch_bounds__(256) void softmax_split_kernel(
    const float* __restrict__ scores,
    u16* __restrict__ ph, u16* __restrict__ pl,
    int mode, const int* __restrict__ vlens)
{
    const int row = blockIdx.x;               // (b*H + h)*S + q
    const int q = row % Ss;
    const int b = row / (Hh * Ss);
    const int valid = (mode == 0) ? (q + 1) : vlens[b];

    const float* p = scores + (size_t)row * Ll;
    const int t = threadIdx.x;
    float x0 = p[t];
    float x1 = p[t + 256];

    __shared__ float red[256];
    float m = -1e30f;
    if (t < valid) m = x0;
    if (t + 256 < valid) m = fmaxf(m, x1);
    red[t] = m; __syncthreads();
#pragma unroll
    for (int s = 128; s > 0; s >>= 1) {
        if (t < s) red[t] = fmaxf(red[t], red[t + s]);
        __syncthreads();
    }
    float mx = red[0];
    __syncthreads();

    float e0 = (t < valid) ? expf(x0 - mx) : 0.0f;
    float e1 = (t + 256 < valid) ? expf(x1 - mx) : 0.0f;
    red[t] = e0 + e1; __syncthreads();
#pragma unroll
    for (int s = 128; s > 0; s >>= 1) {
        if (t < s) red[t] += red[t + s];
        __syncthreads();
    }
    float inv = 1.0f / red[0];
    size_t o = (size_t)row * Ll;
    split1(e0 * inv, ph[o + t], pl[o + t]);
    split1(e1 * inv, ph[o + t + 256], pl[o + t + 256]);
}

// ---------------------------------------------------------------------------
// out = LayerNorm(a + b); optional hi/lo bf16 copy of out.
// ---------------------------------------------------------------------------
__global__ __launch_bounds__(256) void add_ln_kernel(
    const float* __restrict__ a, const float* __restrict__ b,
    const float* __restrict__ w, const float* __restrict__ bs,
    float* __restrict__ out,
    u16* __restrict__ oh, u16* __restrict__ ol)
{
    const int row = blockIdx.x;
    const float* pa = a + (size_t)row * Ee;
    const float* pb = b + (size_t)row * Ee;
    const int t = threadIdx.x;

    float x[3];
    float s = 0.0f;
#pragma unroll
    for (int i = 0; i < 3; i++) {
        x[i] = pa[t + 256 * i] + pb[t + 256 * i];
        s += x[i];
    }
    __shared__ float red[256];
    red[t] = s; __syncthreads();
#pragma unroll
    for (int st = 128; st > 0; st >>= 1) {
        if (t < st) red[t] += red[t + st];
        __syncthreads();
    }
    float mean = red[0] * (1.0f / Ee);
    __syncthreads();

    float v = 0.0f;
#pragma unroll
    for (int i = 0; i < 3; i++) {
        float d = x[i] - mean;
        v += d * d;
    }
    red[t] = v; __syncthreads();
#pragma unroll
    for (int st = 128; st > 0; st >>= 1) {
        if (t < st) red[t] += red[t + st];
        __syncthreads();
    }
    float var = red[0] * (1.0f / Ee);
    float inv = rsqrtf(var + 1e-12f);

#pragma unroll
    for (int i = 0; i < 3; i++) {
        int c = t + 256 * i;
        float o = w[c] * (x[i] - mean) * inv + bs[c];
        size_t off = (size_t)row * Ee + c;
        out[off] = o;
        if (oh) split1(o, oh[off], ol[off]);
    }
}

// ---------------------------------------------------------------------------
// Orchestration
// ---------------------------------------------------------------------------
extern "C" void kernel_launch(void* const* d_in, const int* in_sizes, int n_in,
                              void* d_out, int out_size)
{
    const float* X       = (const float*)d_in[0];
    const float* enc     = (const float*)d_in[1];
    const int*   vlens   = (const int*)  d_in[2];
    const float* w_kx1   = (const float*)d_in[3];
    const float* w_qx1   = (const float*)d_in[4];
    const float* proj1_w = (const float*)d_in[5];
    const float* proj1_b = (const float*)d_in[6];
    const float* ln1_w   = (const float*)d_in[7];
    const float* ln1_b   = (const float*)d_in[8];
    const float* w_kx2   = (const float*)d_in[9];
    const float* w_qx2   = (const float*)d_in[10];
    const float* proj2_w = (const float*)d_in[11];
    const float* proj2_b = (const float*)d_in[12];
    const float* ln2_w   = (const float*)d_in[13];
    const float* ln2_b   = (const float*)d_in[14];
    const float* ffn_w1  = (const float*)d_in[15];
    const float* ffn_b1  = (const float*)d_in[16];
    const float* ffn_w2  = (const float*)d_in[17];
    const float* ffn_b2  = (const float*)d_in[18];
    const float* ln3_w   = (const float*)d_in[19];
    const float* ln3_b   = (const float*)d_in[20];

#define SYM(p, s) cudaGetSymbolAddress((void**)&p, s)
    float *kx, *tmp, *Y, *Z, *sc;
    u16 *Xh,*Xl,*ench,*encl,*kxh,*kxl,*qxh,*qxl,*kxTh,*kxTl;
    u16 *atth,*attl,*hidh,*hidl,*Yh,*Yl,*Zh,*Zl,*sch,*scl;
    u16 *wp0h,*wp0l,*wp1h,*wp1l,*wp2h,*wp2l,*wp3h,*wp3l;
    u16 *pT1h,*pT1l,*pT2h,*pT2l,*fT1h,*fT1l,*fT2h,*fT2l;
    SYM(kx, g_kx); SYM(tmp, g_tmp); SYM(Y, g_Y); SYM(Z, g_Z); SYM(sc, g_sc);
    SYM(Xh, g_Xh); SYM(Xl, g_Xl); SYM(ench, g_ench); SYM(encl, g_encl);
    SYM(kxh, g_kxh); SYM(kxl, g_kxl); SYM(qxh, g_qxh); SYM(qxl, g_qxl);
    SYM(kxTh, g_kxTh); SYM(kxTl, g_kxTl);
    SYM(atth, g_atth); SYM(attl, g_attl); SYM(hidh, g_hidh); SYM(hidl, g_hidl);
    SYM(Yh, g_Yh); SYM(Yl, g_Yl); SYM(Zh, g_Zh); SYM(Zl, g_Zl);
    SYM(sch, g_sch); SYM(scl, g_scl);
    SYM(wp0h, g_wp0h); SYM(wp0l, g_wp0l); SYM(wp1h, g_wp1h); SYM(wp1l, g_wp1l);
    SYM(wp2h, g_wp2h); SYM(wp2l, g_wp2l); SYM(wp3h, g_wp3h); SYM(wp3l, g_wp3l);
    SYM(pT1h, g_pT1h); SYM(pT1l, g_pT1l); SYM(pT2h, g_pT2h); SYM(pT2l, g_pT2l);
    SYM(fT1h, g_fT1h); SYM(fT1l, g_fT1l); SYM(fT2h, g_fT2h); SYM(fT2l, g_fT2l);
#undef SYM

    const int  M    = Bb * Ss;            // 4096
    const long SE   = (long)Ss * Ee;
    const long SL   = (long)Ss * Ll;
    const long HSL  = (long)Hh * SL;
    const long HDS  = (long)HDd * Ss;
    const long HHDS = (long)Hh * HDS;

    auto* G_BIG = gemm_pre<128>;
    auto* G_AV  = gemm_pre<64>;
    const int SM_BIG = 4 * 2 * (128 * 40 + 128 * 40) * 2;   // 163840 B
    const int SM_AV  = 4 * 2 * (128 * 40 + 64 * 40) * 2;    // 122880 B
    cudaFuncSetAttribute(G_BIG, cudaFuncAttributeMaxDynamicSharedMemorySize, SM_BIG);
    cudaFuncSetAttribute(G_AV,  cudaFuncAttributeMaxDynamicSharedMemorySize, SM_AV);

    dim3 gridL(Ee / 128, M / 128, 1);
    dim3 gridS(Ll / 128, Ss / 128, Bb * Hh);
    dim3 gridAV(1, Ss / 128, Bb * Hh);
    dim3 tb(32, 8);
    dim3 gridT768(Ee / 32, Ee / 32, 1);
    dim3 gridTK(Ss / 32, HDd / 32, Bb * Hh);
    const int pblk = (Ee * Ee + 255) / 256;
    const int sblk = (NELE / 4 + 255) / 256;

    // --- prep ---------------------------------------------------------------
    pack_w_split<<<pblk, 256>>>(w_kx1, wp0h, wp0l);
    pack_w_split<<<pblk, 256>>>(w_qx1, wp1h, wp1l);
    pack_w_split<<<pblk, 256>>>(w_kx2, wp2h, wp2l);
    pack_w_split<<<pblk, 256>>>(w_qx2, wp3h, wp3l);
    split_kernel<<<sblk, 256>>>(X, Xh, Xl, NELE / 4);

    // ===================== Self-attention =====================
    G_BIG<<<gridL, 256, SM_BIG>>>(Xh, Xl, Ee, wp0h, wp0l, Ee,
                                  kx, kxh, kxl, Ee, Ee, 1.0f, nullptr, 0,
                                  0, nullptr, 1, 0, 0, 0, 0, 0, 0);
    G_BIG<<<gridL, 256, SM_BIG>>>(Xh, Xl, Ee, wp1h, wp1l, Ee,
                                  nullptr, qxh, qxl, Ee, Ee, 1.0f, nullptr, 0,
                                  0, nullptr, 1, 0, 0, 0, 0, 0, 0);
    transpose_kx_split<<<gridTK, tb>>>(kx, kxTh, kxTl);
    G_BIG<<<gridS, 256, SM_BIG>>>(qxh, qxl, Ee, kxh, kxl, Ee,
                                  sc, nullptr, nullptr, Ll, HDd, 0.125f, nullptr, 0,
                                  1, nullptr,                      // causal block skip
                                  Hh, SE, HDd, SE, HDd, HSL, SL);
    softmax_split_kernel<<<Bb * Hh * Ss, 256>>>(sc, sch, scl, 0, nullptr);
    G_AV<<<gridAV, 256, SM_AV>>>(sch, scl, Ll, kxTh, kxTl, Ss,
                                 nullptr, atth, attl, Ee, Ll, 1.0f, nullptr, 0,
                                 2, nullptr,                       // causal K clamp
                                 Hh, HSL, SL, HHDS, HDS, SE, HDd);
    transpose768_split<<<gridT768, tb>>>(proj1_w, pT1h, pT1l);
    G_BIG<<<gridL, 256, SM_BIG>>>(atth, attl, Ee, pT1h, pT1l, Ee,
                                  tmp, nullptr, nullptr, Ee, Ee, 1.0f, proj1_b, 0,
                                  0, nullptr, 1, 0, 0, 0, 0, 0, 0);
    add_ln_kernel<<<M, 256>>>(tmp, X, ln1_w, ln1_b, Y, Yh, Yl);

    // ===================== Cross-attention =====================
    split_kernel<<<sblk, 256>>>(enc, ench, encl, NELE / 4);
    G_BIG<<<gridL, 256, SM_BIG>>>(ench, encl, Ee, wp2h, wp2l, Ee,
                                  kx, kxh, kxl, Ee, Ee, 1.0f, nullptr, 0,
                                  0, nullptr, 1, 0, 0, 0, 0, 0, 0);
    G_BIG<<<gridL, 256, SM_BIG>>>(Yh, Yl, Ee, wp3h, wp3l, Ee,
                                  nullptr, qxh, qxl, Ee, Ee, 1.0f, nullptr, 0,
                                  0, nullptr, 1, 0, 0, 0, 0, 0, 0);
    transpose_kx_split<<<gridTK, tb>>>(kx, kxTh, kxTl);
    G_BIG<<<gridS, 256, SM_BIG>>>(qxh, qxl, Ee, kxh, kxl, Ee,
                                  sc, nullptr, nullptr, Ll, HDd, 0.125f, nullptr, 0,
                                  3, vlens,                        // padding block skip
                                  Hh, SE, HDd, SE, HDd, HSL, SL);
    softmax_split_kernel<<<Bb * Hh * Ss, 256>>>(sc, sch, scl, 1, vlens);
    G_AV<<<gridAV, 256, SM_AV>>>(sch, scl, Ll, kxTh, kxTl, Ss,
                                 nullptr, atth, attl, Ee, Ll, 1.0f, nullptr, 0,
                                 4, vlens,                         // padding K clamp
                                 Hh, HSL, SL, HHDS, HDS, SE, HDd);
    transpose768_split<<<gridT768, tb>>>(proj2_w, pT2h, pT2l);
    G_BIG<<<gridL, 256, SM_BIG>>>(atth, attl, Ee, pT2h, pT2l, Ee,
                                  tmp, nullptr, nullptr, Ee, Ee, 1.0f, proj2_b, 0,
                                  0, nullptr, 1, 0, 0, 0, 0, 0, 0);
    add_ln_kernel<<<M, 256>>>(tmp, Y, ln2_w, ln2_b, Z, Zh, Zl);

    // ===================== FFN =====================
    transpose768_split<<<gridT768, tb>>>(ffn_w1, fT1h, fT1l);
    transpose768_split<<<gridT768, tb>>>(ffn_w2, fT2h, fT2l);
    G_BIG<<<gridL, 256, SM_BIG>>>(Zh, Zl, Ee, fT1h, fT1l, Ee,
                                  nullptr, hidh, hidl, Ee, Ee, 1.0f, ffn_b1, 1,
                                  0, nullptr, 1, 0, 0, 0, 0, 0, 0);
    G_BIG<<<gridL, 256, SM_BIG>>>(hidh, hidl, Ee, fT2h, fT2l, Ee,
                                  tmp, nullptr, nullptr, Ee, Ee, 1.0f, ffn_b2, 0,
                                  0, nullptr, 1, 0, 0, 0, 0, 0, 0);
    add_ln_kernel<<<M, 256>>>(tmp, Z, ln3_w, ln3_b, (float*)d_out, nullptr, nullptr);
}

// round 13
// speedup vs baseline: 1.4014x; 1.3232x over previous
#include <cuda_runtime.h>
#include <math.h>
#include <stdint.h>

// Problem constants
#define Bb 8
#define Ss 512
#define Ll 512
#define Ee 768
#define Hh 12
#define HDd 64

#define NELE (Bb * Ss * Ee)                       // 3145728
#define NSC  ((size_t)Bb * Hh * Ss * Ll)          // 25165824

typedef unsigned short u16;

// ---------------------------------------------------------------------------
// Scratch (device globals — no allocation allowed)
// ---------------------------------------------------------------------------
__device__ float g_kx [NELE];
__device__ float g_tmp[NELE];
__device__ float g_Y  [NELE];
__device__ float g_Z  [NELE];
__device__ float g_sc [NSC];

__device__ u16 g_Xh[NELE],   g_Xl[NELE];
__device__ u16 g_ench[NELE], g_encl[NELE];
__device__ u16 g_kxh[NELE],  g_kxl[NELE];
__device__ u16 g_qxh[NELE],  g_qxl[NELE];
__device__ u16 g_kxTh[NELE], g_kxTl[NELE];       // [(b*H+h)*64+d][l]
__device__ u16 g_atth[NELE], g_attl[NELE];
__device__ u16 g_hidh[NELE], g_hidl[NELE];
__device__ u16 g_Yh[NELE],   g_Yl[NELE];
__device__ u16 g_Zh[NELE],   g_Zl[NELE];
__device__ u16 g_sch[NSC],   g_scl[NSC];
__device__ u16 g_wp0h[Ee*Ee], g_wp0l[Ee*Ee];
__device__ u16 g_wp1h[Ee*Ee], g_wp1l[Ee*Ee];
__device__ u16 g_wp2h[Ee*Ee], g_wp2l[Ee*Ee];
__device__ u16 g_wp3h[Ee*Ee], g_wp3l[Ee*Ee];
__device__ u16 g_pT1h[Ee*Ee], g_pT1l[Ee*Ee];
__device__ u16 g_pT2h[Ee*Ee], g_pT2l[Ee*Ee];
__device__ u16 g_fT1h[Ee*Ee], g_fT1l[Ee*Ee];
__device__ u16 g_fT2h[Ee*Ee], g_fT2l[Ee*Ee];

// ---------------------------------------------------------------------------
// fp32 <-> bf16 hi/lo split helpers
// ---------------------------------------------------------------------------
__device__ __forceinline__ u16 f2bf(float f) {
    unsigned u = __float_as_uint(f);
    u += 0x7FFFu + ((u >> 16) & 1u);
    return (u16)(u >> 16);
}
__device__ __forceinline__ float bf2f(u16 h) {
    return __uint_as_float(((unsigned)h) << 16);
}
__device__ __forceinline__ void split1(float x, u16 &h, u16 &l) {
    h = f2bf(x);
    l = f2bf(x - bf2f(h));
}
__device__ __forceinline__ void split2(float x, float y, unsigned &hi, unsigned &lo) {
    u16 hx, lx, hy, ly;
    split1(x, hx, lx); split1(y, hy, ly);
    hi = (unsigned)hx | ((unsigned)hy << 16);
    lo = (unsigned)lx | ((unsigned)ly << 16);
}

__device__ __forceinline__ void mma16816(float* c, const unsigned* a, unsigned b0, unsigned b1) {
    asm volatile(
        "mma.sync.aligned.m16n8k16.row.col.f32.bf16.bf16.f32 "
        "{%0,%1,%2,%3}, {%4,%5,%6,%7}, {%8,%9}, {%0,%1,%2,%3};\n"
        : "+f"(c[0]), "+f"(c[1]), "+f"(c[2]), "+f"(c[3])
        : "r"(a[0]), "r"(a[1]), "r"(a[2]), "r"(a[3]), "r"(b0), "r"(b1));
}

__device__ __forceinline__ void ldsm4(unsigned &r0, unsigned &r1, unsigned &r2, unsigned &r3,
                                      uint32_t a) {
    asm volatile("ldmatrix.sync.aligned.m8n8.x4.shared.b16 {%0,%1,%2,%3}, [%4];"
                 : "=r"(r0), "=r"(r1), "=r"(r2), "=r"(r3) : "r"(a));
}

__device__ __forceinline__ uint32_t s2u32(const void* p) {
    uint32_t a;
    asm("{ .reg .u64 t; cvta.to.shared.u64 t, %1; cvt.u32.u64 %0, t; }" : "=r"(a) : "l"(p));
    return a;
}

// ---------------------------------------------------------------------------
// Prep kernels
// ---------------------------------------------------------------------------
// w[h][e][d] -> wp[n=h*64+d][e], hi/lo.  Coalesced both sides via SMEM tile.
// grid (Ee/32, HDd/32, Hh), block (32, 8).
__global__ void pack_w_split(const float* __restrict__ w,
                             u16* __restrict__ oh, u16* __restrict__ ol) {
    __shared__ float t[32][33];
    int h = blockIdx.z;
    int e0 = blockIdx.x * 32, d0 = blockIdx.y * 32;
    int tx = threadIdx.x, ty = threadIdx.y;
#pragma unroll
    for (int i = 0; i < 32; i += 8)
        t[ty + i][tx] = w[((size_t)h * Ee + e0 + ty + i) * HDd + d0 + tx];
    __syncthreads();
#pragma unroll
    for (int i = 0; i < 32; i += 8) {
        size_t o = (size_t)(h * HDd + d0 + ty + i) * Ee + e0 + tx;
        split1(t[tx][ty + i], oh[o], ol[o]);
    }
}

__global__ void split_kernel(const float* __restrict__ in,
                             u16* __restrict__ oh, u16* __restrict__ ol, int n4) {
    int i = blockIdx.x * blockDim.x + threadIdx.x;
    if (i >= n4) return;
    float4 v = ((const float4*)in)[i];
    unsigned h0, l0, h1, l1;
    split2(v.x, v.y, h0, l0);
    split2(v.z, v.w, h1, l1);
    ((uint2*)oh)[i] = make_uint2(h0, h1);
    ((uint2*)ol)[i] = make_uint2(l0, l1);
}

__global__ void transpose768_split(const float* __restrict__ in,
                                   u16* __restrict__ oh, u16* __restrict__ ol) {
    __shared__ float t[32][33];
    int x0 = blockIdx.x * 32, y0 = blockIdx.y * 32;
    int tx = threadIdx.x, ty = threadIdx.y;
#pragma unroll
    for (int i = 0; i < 32; i += 8)
        t[ty + i][tx] = in[(size_t)(y0 + ty + i) * Ee + x0 + tx];
    __syncthreads();
#pragma unroll
    for (int i = 0; i < 32; i += 8) {
        size_t o = (size_t)(x0 + ty + i) * Ee + y0 + tx;
        split1(t[tx][ty + i], oh[o], ol[o]);
    }
}

__global__ void transpose_kx_split(const float* __restrict__ kx,
                                   u16* __restrict__ oh, u16* __restrict__ ol) {
    __shared__ float t[32][33];
    int bh = blockIdx.z;
    int b = bh / Hh, h = bh % Hh;
    int l0 = blockIdx.x * 32, d0 = blockIdx.y * 32;
    int tx = threadIdx.x, ty = threadIdx.y;
#pragma unroll
    for (int i = 0; i < 32; i += 8)
        t[ty + i][tx] = kx[(size_t)(b * Ss + l0 + ty + i) * Ee + h * HDd + d0 + tx];
    __syncthreads();
#pragma unroll
    for (int i = 0; i < 32; i += 8) {
        size_t o = ((size_t)bh * HDd + d0 + ty + i) * Ss + l0 + tx;
        split1(t[tx][ty + i], oh[o], ol[o]);
    }
}

// ---------------------------------------------------------------------------
// Pre-split bf16x3 NT GEMM: mma.sync + ldmatrix.x4, 2-stage cp.async,
// 2 CTAs/SM.  C = act(alpha * A@B^T (+bias))
// mmode: 0 none; 1 causal-scores skip; 2 causal-AV K clamp;
//        3 pad-scores skip; 4 pad-AV K clamp.  (exact zeros only)
// ---------------------------------------------------------------------------
template <int BN>
__global__ __launch_bounds__(256, 2) void gemm_pre(
    const u16* __restrict__ Ah, const u16* __restrict__ Al, int lda,
    const u16* __restrict__ Bh, const u16* __restrict__ Bl, int ldb,
    float* __restrict__ Cf, u16* __restrict__ Chi, u16* __restrict__ Clo,
    int ldc, int K, float alpha, const float* __restrict__ bias, int act,
    int mmode, const int* __restrict__ vl,
    int divz, long sA1, long sA2, long sB1, long sB2, long sC1, long sC2)
{
    constexpr int BM = 128, BK = 32, BKp = 40;
    constexpr int ASZ = BM * BKp, BSZ = BN * BKp;       // shorts per array
    constexpr int STG = 2 * (ASZ + BSZ);                // shorts per stage
    constexpr int WN = 32, WM = (BN == 128) ? 64 : 32;
    constexpr int MF = WM / 16, NF = WN / 8;
    extern __shared__ __align__(16) u16 smx[];

    const int z = blockIdx.z, z1 = z / divz, z2 = z % divz;
    const long aoff = z1 * sA1 + z2 * sA2;
    const long boff = z1 * sB1 + z2 * sB2;
    const long coff = z1 * sC1 + z2 * sC2;
    Ah += aoff; Al += aoff; Bh += boff; Bl += boff;

    const int tid = threadIdx.x, w = tid >> 5, lane = tid & 31;
    const int g = lane >> 2, tig = lane & 3;
    const int bm0 = blockIdx.y * BM, bn0 = blockIdx.x * BN;
    const int wm0 = (w / (BN / WN)) * WM;
    const int wn0 = (w % (BN / WN)) * WN;

    // --- masked-structure work elimination (exact zeros only) ---------------
    int kmax = K;
    if (mmode == 1) {
        if (bn0 >= bm0 + BM) return;
    } else if (mmode == 2) {
        kmax = bm0 + BM; if (kmax > K) kmax = K;
    } else if (mmode == 3) {
        if (vl[z1] <= bn0) return;
    } else if (mmode == 4) {
        int v = vl[z1];
        kmax = ((v + BK - 1) / BK) * BK;
        if (kmax > K) kmax = K;
    }

    const uint32_t smem0 = s2u32(smx);
    const int r8 = lane & 7, grp = lane >> 3;
    const uint32_t offA = (uint32_t)(((r8 + (grp & 1) * 8) * BKp + (grp >> 1) * 8) * 2);
    const uint32_t offB = (uint32_t)(((r8 + (lane >> 4) * 8) * BKp + ((grp & 1)) * 8) * 2);

    float cacc[MF][NF][4];
#pragma unroll
    for (int mf = 0; mf < MF; mf++)
#pragma unroll
        for (int nf = 0; nf < NF; nf++)
#pragma unroll
            for (int i = 0; i < 4; i++) cacc[mf][nf][i] = 0.0f;

    auto load_stage = [&](int s, int k0) {
        u16* base = smx + s * STG;
#pragma unroll
        for (int arr = 0; arr < 2; arr++) {
            u16* d0 = base + arr * ASZ;
            const u16* src = arr ? Al : Ah;
            for (int c = tid; c < BM * 4; c += 256) {
                int r = c >> 2, ch = c & 3;
                uint32_t da = (uint32_t)__cvta_generic_to_shared(d0 + r * BKp + ch * 8);
                const void* sa = src + (size_t)(bm0 + r) * lda + k0 + ch * 8;
                asm volatile("cp.async.cg.shared.global [%0], [%1], 16;\n" :: "r"(da), "l"(sa));
            }
        }
#pragma unroll
        for (int arr = 0; arr < 2; arr++) {
            u16* d0 = base + 2 * ASZ + arr * BSZ;
            const u16* src = arr ? Bl : Bh;
            for (int c = tid; c < BN * 4; c += 256) {
                int r = c >> 2, ch = c & 3;
                uint32_t da = (uint32_t)__cvta_generic_to_shared(d0 + r * BKp + ch * 8);
                const void* sa = src + (size_t)(bn0 + r) * ldb + k0 + ch * 8;
                asm volatile("cp.async.cg.shared.global [%0], [%1], 16;\n" :: "r"(da), "l"(sa));
            }
        }
        asm volatile("cp.async.commit_group;\n");
    };

    const int T = kmax / BK;
    load_stage(0, 0);
    if (T > 1) load_stage(1, BK);

    for (int t = 0; t < T; t++) {
        if (t < T - 1) asm volatile("cp.async.wait_group 1;\n" ::: "memory");
        else           asm volatile("cp.async.wait_group 0;\n" ::: "memory");
        __syncthreads();

        const uint32_t sb    = smem0 + (uint32_t)((t & 1) * STG * 2);
        const uint32_t aBase = sb + (uint32_t)(wm0 * BKp * 2) + offA;
        const uint32_t bBase = sb + (uint32_t)(2 * ASZ * 2 + wn0 * BKp * 2) + offB;

#pragma unroll
        for (int ks = 0; ks < 2; ks++) {
            unsigned bh[NF][2], bl[NF][2];
#pragma unroll
            for (int p = 0; p < NF / 2; p++) {
                uint32_t ad = bBase + (uint32_t)((p * 16 * BKp + ks * 16) * 2);
                ldsm4(bh[2*p][0], bh[2*p][1], bh[2*p+1][0], bh[2*p+1][1], ad);
                ldsm4(bl[2*p][0], bl[2*p][1], bl[2*p+1][0], bl[2*p+1][1], ad + BSZ * 2);
            }
#pragma unroll
            for (int mf = 0; mf < MF; mf++) {
                uint32_t ad = aBase + (uint32_t)((mf * 16 * BKp + ks * 16) * 2);
                unsigned ah[4], al[4];
                ldsm4(ah[0], ah[1], ah[2], ah[3], ad);
                ldsm4(al[0], al[1], al[2], al[3], ad + ASZ * 2);
                // term-major within mf: per-accumulator order stays hh,lh,hl
                // (bitwise identical); dependency distance 1 -> NF.
#pragma unroll
                for (int nf = 0; nf < NF; nf++)
                    mma16816(cacc[mf][nf], ah, bh[nf][0], bh[nf][1]);   // hi*hi
#pragma unroll
                for (int nf = 0; nf < NF; nf++)
                    mma16816(cacc[mf][nf], al, bh[nf][0], bh[nf][1]);   // lo*hi
#pragma unroll
                for (int nf = 0; nf < NF; nf++)
                    mma16816(cacc[mf][nf], ah, bl[nf][0], bl[nf][1]);   // hi*lo
            }
        }
        __syncthreads();                       // readers done before refill
        if (t + 2 < T) load_stage(t & 1, (t + 2) * BK);
    }

    // Epilogue
#pragma unroll
    for (int mf = 0; mf < MF; mf++) {
#pragma unroll
        for (int nf = 0; nf < NF; nf++) {
            int row = bm0 + wm0 + mf * 16 + g;
            int col = bn0 + wn0 + nf * 8 + tig * 2;
            float b0 = 0.f, b1 = 0.f;
            if (bias) { b0 = bias[col]; b1 = bias[col + 1]; }
            float v0 = cacc[mf][nf][0] * alpha + b0;
            float v1 = cacc[mf][nf][1] * alpha + b1;
            float v2 = cacc[mf][nf][2] * alpha + b0;
            float v3 = cacc[mf][nf][3] * alpha + b1;
            if (act) {
                v0 = 0.5f * v0 * (1.0f + erff(v0 * 0.70710678118654752f));
                v1 = 0.5f * v1 * (1.0f + erff(v1 * 0.70710678118654752f));
                v2 = 0.5f * v2 * (1.0f + erff(v2 * 0.70710678118654752f));
                v3 = 0.5f * v3 * (1.0f + erff(v3 * 0.70710678118654752f));
            }
            size_t o0 = coff + (size_t)row * ldc + col;
            size_t o1 = coff + (size_t)(row + 8) * ldc + col;
            if (Cf) {
                *(float2*)&Cf[o0] = make_float2(v0, v1);
                *(float2*)&Cf[o1] = make_float2(v2, v3);
            }
            if (Chi) {
                unsigned h0, l0, h1, l1;
                split2(v0, v1, h0, l0);
                split2(v2, v3, h1, l1);
                *(unsigned*)&Chi[o0] = h0; *(unsigned*)&Clo[o0] = l0;
                *(unsigned*)&Chi[o1] = h1; *(unsigned*)&Clo[o1] = l1;
            }
        }
    }
}

// ---------------------------------------------------------------------------
// Warp-per-row masked softmax: fp32 scores in, hi/lo bf16 probs out.
// 8 rows per 256-thread block; shuffle reductions, no __syncthreads.
// ---------------------------------------------------------------------------
__global__ __launch_bounds__(256) void softmax_split_kernel(
    const float* __restrict__ scores,
    u16* __restrict__ ph, u16* __restrict__ pl,
    int mode, const int* __restrict__ vlens)
{
    const int wid = threadIdx.x >> 5, lane = threadIdx.x & 31;
    const int row = blockIdx.x * 8 + wid;     // (b*H + h)*S + q
    const int q = row % Ss;
    const int b = row / (Hh * Ss);
    const int valid = (mode == 0) ? (q + 1) : vlens[b];

    const float* p = scores + (size_t)row * Ll;
    float x[16];
    float m = -1e30f;
#pragma unroll
    for (int i = 0; i < 16; i++) {
        int c = lane + 32 * i;
        x[i] = (c < valid) ? p[c] : -1e30f;
        m = fmaxf(m, x[i]);
    }
#pragma unroll
    for (int o = 16; o > 0; o >>= 1)
        m = fmaxf(m, __shfl_xor_sync(0xFFFFFFFFu, m, o));

    float s = 0.0f;
#pragma unroll
    for (int i = 0; i < 16; i++) {
        int c = lane + 32 * i;
        float e = (c < valid) ? expf(x[i] - m) : 0.0f;
        x[i] = e;
        s += e;
    }
#pragma unroll
    for (int o = 16; o > 0; o >>= 1)
        s += __shfl_xor_sync(0xFFFFFFFFu, s, o);
    float inv = 1.0f / s;

    size_t o = (size_t)row * Ll;
#pragma unroll
    for (int i = 0; i < 16; i++) {
        u16 hh, ll;
        split1(x[i] * inv, hh, ll);
        ph[o + lane + 32 * i] = hh;
        pl[o + lane + 32 * i] = ll;
    }
}

// ---------------------------------------------------------------------------
// out = LayerNorm(a + b); optional hi/lo bf16 copy.  Shuffle reductions.
// ---------------------------------------------------------------------------
__global__ __launch_bounds__(256) void add_ln_kernel(
    const float* __restrict__ a, const float* __restrict__ b,
    const float* __restrict__ w, const float* __restrict__ bs,
    float* __restrict__ out,
    u16* __restrict__ oh, u16* __restrict__ ol)
{
    const int row = blockIdx.x;
    const float* pa = a + (size_t)row * Ee;
    const float* pb = b + (size_t)row * Ee;
    const int t = threadIdx.x;
    const int wid = t >> 5, lane = t & 31;
    __shared__ float red[8];

    float x[3];
    float s = 0.0f;
#pragma unroll
    for (int i = 0; i < 3; i++) {
        x[i] = pa[t + 256 * i] + pb[t + 256 * i];
        s += x[i];
    }
#pragma unroll
    for (int o = 16; o > 0; o >>= 1) s += __shfl_xor_sync(0xFFFFFFFFu, s, o);
    if (lane == 0) red[wid] = s;
    __syncthreads();
    float tot = 0.0f;
#pragma unroll
    for (int i = 0; i < 8; i++) tot += red[i];
    float mean = tot * (1.0f / Ee);
    __syncthreads();

    float v = 0.0f;
#pragma unroll
    for (int i = 0; i < 3; i++) {
        float d = x[i] - mean;
        v += d * d;
    }
#pragma unroll
    for (int o = 16; o > 0; o >>= 1) v += __shfl_xor_sync(0xFFFFFFFFu, v, o);
    if (lane == 0) red[wid] = v;
    __syncthreads();
    float vtot = 0.0f;
#pragma unroll
    for (int i = 0; i < 8; i++) vtot += red[i];
    float inv = rsqrtf(vtot * (1.0f / Ee) + 1e-12f);

#pragma unroll
    for (int i = 0; i < 3; i++) {
        int c = t + 256 * i;
        float o = w[c] * (x[i] - mean) * inv + bs[c];
        size_t off = (size_t)row * Ee + c;
        out[off] = o;
        if (oh) split1(o, oh[off], ol[off]);
    }
}

// ---------------------------------------------------------------------------
// Orchestration
// ---------------------------------------------------------------------------
extern "C" void kernel_launch(void* const* d_in, const int* in_sizes, int n_in,
                              void* d_out, int out_size)
{
    const float* X       = (const float*)d_in[0];
    const float* enc     = (const float*)d_in[1];
    const int*   vlens   = (const int*)  d_in[2];
    const float* w_kx1   = (const float*)d_in[3];
    const float* w_qx1   = (const float*)d_in[4];
    const float* proj1_w = (const float*)d_in[5];
    const float* proj1_b = (const float*)d_in[6];
    const float* ln1_w   = (const float*)d_in[7];
    const float* ln1_b   = (const float*)d_in[8];
    const float* w_kx2   = (const float*)d_in[9];
    const float* w_qx2   = (const float*)d_in[10];
    const float* proj2_w = (const float*)d_in[11];
    const float* proj2_b = (const float*)d_in[12];
    const float* ln2_w   = (const float*)d_in[13];
    const float* ln2_b   = (const float*)d_in[14];
    const float* ffn_w1  = (const float*)d_in[15];
    const float* ffn_b1  = (const float*)d_in[16];
    const float* ffn_w2  = (const float*)d_in[17];
    const float* ffn_b2  = (const float*)d_in[18];
    const float* ln3_w   = (const float*)d_in[19];
    const float* ln3_b   = (const float*)d_in[20];

#define SYM(p, s) cudaGetSymbolAddress((void**)&p, s)
    float *kx, *tmp, *Y, *Z, *sc;
    u16 *Xh,*Xl,*ench,*encl,*kxh,*kxl,*qxh,*qxl,*kxTh,*kxTl;
    u16 *atth,*attl,*hidh,*hidl,*Yh,*Yl,*Zh,*Zl,*sch,*scl;
    u16 *wp0h,*wp0l,*wp1h,*wp1l,*wp2h,*wp2l,*wp3h,*wp3l;
    u16 *pT1h,*pT1l,*pT2h,*pT2l,*fT1h,*fT1l,*fT2h,*fT2l;
    SYM(kx, g_kx); SYM(tmp, g_tmp); SYM(Y, g_Y); SYM(Z, g_Z); SYM(sc, g_sc);
    SYM(Xh, g_Xh); SYM(Xl, g_Xl); SYM(ench, g_ench); SYM(encl, g_encl);
    SYM(kxh, g_kxh); SYM(kxl, g_kxl); SYM(qxh, g_qxh); SYM(qxl, g_qxl);
    SYM(kxTh, g_kxTh); SYM(kxTl, g_kxTl);
    SYM(atth, g_atth); SYM(attl, g_attl); SYM(hidh, g_hidh); SYM(hidl, g_hidl);
    SYM(Yh, g_Yh); SYM(Yl, g_Yl); SYM(Zh, g_Zh); SYM(Zl, g_Zl);
    SYM(sch, g_sch); SYM(scl, g_scl);
    SYM(wp0h, g_wp0h); SYM(wp0l, g_wp0l); SYM(wp1h, g_wp1h); SYM(wp1l, g_wp1l);
    SYM(wp2h, g_wp2h); SYM(wp2l, g_wp2l); SYM(wp3h, g_wp3h); SYM(wp3l, g_wp3l);
    SYM(pT1h, g_pT1h); SYM(pT1l, g_pT1l); SYM(pT2h, g_pT2h); SYM(pT2l, g_pT2l);
    SYM(fT1h, g_fT1h); SYM(fT1l, g_fT1l); SYM(fT2h, g_fT2h); SYM(fT2l, g_fT2l);
#undef SYM

    const int  M    = Bb * Ss;            // 4096
    const long SE   = (long)Ss * Ee;
    const long SL   = (long)Ss * Ll;
    const long HSL  = (long)Hh * SL;
    const long HDS  = (long)HDd * Ss;
    const long HHDS = (long)Hh * HDS;

    auto* G_BIG = gemm_pre<128>;
    auto* G_AV  = gemm_pre<64>;
    // 2 stages: stage shorts = 2*(128*40 + BN*40); bytes = *2
    const int SM_BIG = 2 * 2 * (128 * 40 + 128 * 40) * 2;   // 81920 B  (2 CTAs/SM)
    const int SM_AV  = 2 * 2 * (128 * 40 + 64 * 40) * 2;    // 61440 B  (2 CTAs/SM)
    cudaFuncSetAttribute(G_BIG, cudaFuncAttributeMaxDynamicSharedMemorySize, SM_BIG);
    cudaFuncSetAttribute(G_AV,  cudaFuncAttributeMaxDynamicSharedMemorySize, SM_AV);

    dim3 gridL(Ee / 128, M / 128, 1);
    dim3 gridS(Ll / 128, Ss / 128, Bb * Hh);
    dim3 gridAV(1, Ss / 128, Bb * Hh);
    dim3 tb(32, 8);
    dim3 gridT768(Ee / 32, Ee / 32, 1);
    dim3 gridTK(Ss / 32, HDd / 32, Bb * Hh);
    dim3 gridPW(Ee / 32, HDd / 32, Hh);
    const int sblk = (NELE / 4 + 255) / 256;
    const int smgrid = Bb * Hh * Ss / 8;   // 6144

    // --- prep ---------------------------------------------------------------
    pack_w_split<<<gridPW, tb>>>(w_kx1, wp0h, wp0l);
    pack_w_split<<<gridPW, tb>>>(w_qx1, wp1h, wp1l);
    pack_w_split<<<gridPW, tb>>>(w_kx2, wp2h, wp2l);
    pack_w_split<<<gridPW, tb>>>(w_qx2, wp3h, wp3l);
    split_kernel<<<sblk, 256>>>(X, Xh, Xl, NELE / 4);

    // ===================== Self-attention =====================
    G_BIG<<<gridL, 256, SM_BIG>>>(Xh, Xl, Ee, wp0h, wp0l, Ee,
                                  kx, kxh, kxl, Ee, Ee, 1.0f, nullptr, 0,
                                  0, nullptr, 1, 0, 0, 0, 0, 0, 0);
    G_BIG<<<gridL, 256, SM_BIG>>>(Xh, Xl, Ee, wp1h, wp1l, Ee,
                                  nullptr, qxh, qxl, Ee, Ee, 1.0f, nullptr, 0,
                                  0, nullptr, 1, 0, 0, 0, 0, 0, 0);
    transpose_kx_split<<<gridTK, tb>>>(kx, kxTh, kxTl);
    G_BIG<<<gridS, 256, SM_BIG>>>(qxh, qxl, Ee, kxh, kxl, Ee,
                                  sc, nullptr, nullptr, Ll, HDd, 0.125f, nullptr, 0,
                                  1, nullptr,                      // causal block skip
                                  Hh, SE, HDd, SE, HDd, HSL, SL);
    softmax_split_kernel<<<smgrid, 256>>>(sc, sch, scl, 0, nullptr);
    G_AV<<<gridAV, 256, SM_AV>>>(sch, scl, Ll, kxTh, kxTl, Ss,
                                 nullptr, atth, attl, Ee, Ll, 1.0f, nullptr, 0,
                                 2, nullptr,                       // causal K clamp
                                 Hh, HSL, SL, HHDS, HDS, SE, HDd);
    transpose768_split<<<gridT768, tb>>>(proj1_w, pT1h, pT1l);
    G_BIG<<<gridL, 256, SM_BIG>>>(atth, attl, Ee, pT1h, pT1l, Ee,
                                  tmp, nullptr, nullptr, Ee, Ee, 1.0f, proj1_b, 0,
                                  0, nullptr, 1, 0, 0, 0, 0, 0, 0);
    add_ln_kernel<<<M, 256>>>(tmp, X, ln1_w, ln1_b, Y, Yh, Yl);

    // ===================== Cross-attention =====================
    split_kernel<<<sblk, 256>>>(enc, ench, encl, NELE / 4);
    G_BIG<<<gridL, 256, SM_BIG>>>(ench, encl, Ee, wp2h, wp2l, Ee,
                                  kx, kxh, kxl, Ee, Ee, 1.0f, nullptr, 0,
                                  0, nullptr, 1, 0, 0, 0, 0, 0, 0);
    G_BIG<<<gridL, 256, SM_BIG>>>(Yh, Yl, Ee, wp3h, wp3l, Ee,
                                  nullptr, qxh, qxl, Ee, Ee, 1.0f, nullptr, 0,
                                  0, nullptr, 1, 0, 0, 0, 0, 0, 0);
    transpose_kx_split<<<gridTK, tb>>>(kx, kxTh, kxTl);
    G_BIG<<<gridS, 256, SM_BIG>>>(qxh, qxl, Ee, kxh, kxl, Ee,
                                  sc, nullptr, nullptr, Ll, HDd, 0.125f, nullptr, 0,
                                  3, vlens,                        // padding block skip
                                  Hh, SE, HDd, SE, HDd, HSL, SL);
    softmax_split_kernel<<<smgrid, 256>>>(sc, sch, scl, 1, vlens);
    G_AV<<<gridAV, 256, SM_AV>>>(sch, scl, Ll, kxTh, kxTl, Ss,
                                 nullptr, atth, attl, Ee, Ll, 1.0f, nullptr, 0,
                                 4, vlens,                         // padding K clamp
                                 Hh, HSL, SL, HHDS, HDS, SE, HDd);
    transpose768_split<<<gridT768, tb>>>(proj2_w, pT2h, pT2l);
    G_BIG<<<gridL, 256, SM_BIG>>>(atth, attl, Ee, pT2h, pT2l, Ee,
                                  tmp, nullptr, nullptr, Ee, Ee, 1.0f, proj2_b, 0,
                                  0, nullptr, 1, 0, 0, 0, 0, 0, 0);
    add_ln_kernel<<<M, 256>>>(tmp, Y, ln2_w, ln2_b, Z, Zh, Zl);

    // ===================== FFN =====================
    transpose768_split<<<gridT768, tb>>>(ffn_w1, fT1h, fT1l);
    transpose768_split<<<gridT768, tb>>>(ffn_w2, fT2h, fT2l);
    G_BIG<<<gridL, 256, SM_BIG>>>(Zh, Zl, Ee, fT1h, fT1l, Ee,
                                  nullptr, hidh, hidl, Ee, Ee, 1.0f, ffn_b1, 1,
                                  0, nullptr, 1, 0, 0, 0, 0, 0, 0);
    G_BIG<<<gridL, 256, SM_BIG>>>(hidh, hidl, Ee, fT2h, fT2l, Ee,
                                  tmp, nullptr, nullptr, Ee, Ee, 1.0f, ffn_b2, 0,
                                  0, nullptr, 1, 0, 0, 0, 0, 0, 0);
    add_ln_kernel<<<M, 256>>>(tmp, Z, ln3_w, ln3_b, (float*)d_out, nullptr, nullptr);
}